// round 17
// baseline (speedup 1.0000x reference)
#include <cuda_runtime.h>
#include <cuda_fp16.h>
#include <math.h>
#include <cstdint>

typedef unsigned int u32;
typedef unsigned long long ull;

#define NCTA 128
#define NTHR 288          // 8 compute warps + 1 W-producer warp
#define HS_  33554432ull
#define BH_  65536
// W-ring 3x16KB + 32KB zbuf + barriers
#define SMEM_DYN 81968

__device__ __align__(16) u32 g_W[15728640];      // fp16 weight images (60MB), B-fragment order
__device__ __align__(16) u32 g_x[16777216];      // fp16 hi/lo x images, A-fragment order
__device__ __align__(16) u32 g_hA[2][4][65536];  // fp16 hi/lo h images [parity][layer]
__device__ unsigned g_sync[2];                   // [0]=count, [1]=generation (relative use only)

__device__ __forceinline__ u32 sm_u32(const void* p) {
    u32 a;
    asm("{.reg .u64 t; cvta.to.shared.u64 t, %1; cvt.u32.u64 %0, t;}" : "=r"(a) : "l"(p));
    return a;
}
__device__ __forceinline__ void bulk_cp(u32 dst, const void* src, u32 bytes, u32 mbar) {
    asm volatile("cp.async.bulk.shared::cluster.global.mbarrier::complete_tx::bytes "
                 "[%0], [%1], %2, [%3];" :: "r"(dst), "l"(src), "r"(bytes), "r"(mbar) : "memory");
}
__device__ __forceinline__ void mbar_init(u32 a, u32 c) {
    asm volatile("mbarrier.init.shared.b64 [%0], %1;" :: "r"(a), "r"(c) : "memory");
}
__device__ __forceinline__ void mbar_expect(u32 a, u32 tx) {
    asm volatile("mbarrier.arrive.expect_tx.shared.b64 _, [%0], %1;" :: "r"(a), "r"(tx) : "memory");
}
__device__ __forceinline__ void mbar_arrive(u32 a) {
    asm volatile("mbarrier.arrive.shared.b64 _, [%0];" :: "r"(a) : "memory");
}
__device__ __forceinline__ void mbar_wait(u32 a, u32 ph) {
    u32 done = 0;
    while (!done)
        asm volatile("{.reg .pred p; mbarrier.try_wait.parity.acquire.cta.shared::cta.b64 "
                     "p, [%1], %2, 0x989680; selp.b32 %0,1,0,p;}"
                     : "=r"(done) : "r"(a), "r"(ph) : "memory");
}
__device__ __forceinline__ void mma16816(float* c, const u32* a, const u32* b) {
    asm("mma.sync.aligned.m16n8k16.row.col.f32.f16.f16.f32 "
        "{%0,%1,%2,%3}, {%4,%5,%6,%7}, {%8,%9}, {%0,%1,%2,%3};"
        : "+f"(c[0]), "+f"(c[1]), "+f"(c[2]), "+f"(c[3])
        : "r"(a[0]), "r"(a[1]), "r"(a[2]), "r"(a[3]), "r"(b[0]), "r"(b[1]));
}
__device__ __forceinline__ u32 pack2h(float v0, float v1, bool lo) {
    __half h0 = __float2half_rn(v0), h1 = __float2half_rn(v1);
    if (lo) {
        h0 = __float2half_rn(v0 - __half2float(h0));
        h1 = __float2half_rn(v1 - __half2float(h1));
    }
    u32 u0 = (u32)__half_as_ushort(h0), u1 = (u32)__half_as_ushort(h1);
    return u0 | (u1 << 16);
}
__device__ __forceinline__ float fsig(float x) {
    return __fdividef(1.f, 1.f + __expf(-x));
}
__device__ __forceinline__ float ftanh(float x) {
    const float e = __expf(-2.f * x);
    return __fdividef(1.f - e, 1.f + e);
}
#define CBAR() asm volatile("bar.sync 1, 256;" ::: "memory")
#define GEN()  (*(volatile unsigned*)&g_sync[1])

// grid barrier over compute warps only (t < 256).
__device__ __forceinline__ void grid_sync_c() {
    CBAR();
    if (threadIdx.x == 0) {
        __threadfence();
        unsigned gen = GEN();
        if (atomicAdd(&g_sync[0], 1u) == NCTA - 1u) {
            g_sync[0] = 0;
            __threadfence();
            GEN() = gen + 1u;
        } else {
            while (GEN() == gen) __nanosleep(32);
        }
        __threadfence();
    }
    CBAR();
}

__global__ void __launch_bounds__(NTHR, 1)
lstm_persist(const float* __restrict__ x,
             const float* __restrict__ Wx0, const float* __restrict__ Wh0,
             const float* __restrict__ b0,
             const float* __restrict__ Wxr, const float* __restrict__ Whr,
             const float* __restrict__ br,
             float* __restrict__ out)
{
    extern __shared__ __align__(16) u32 sm[];
    // layout (u32): W-ring [0,12288), zbuf [12288,20480)
    float* zbuf = (float*)(sm + 12288);
    const u32 smb = sm_u32(sm);
    const u32 mbF  = smb + 81920u;   // full[3], arrive count 1 (W producer)
    const u32 mbEW = smb + 81944u;   // W empty[3]

    const int t = threadIdx.x, lane = t & 31, wid = t >> 5;

    // ================= PROLOGUE: image prep (grid-strided, all warps) =======
    for (int z = blockIdx.x * NTHR + t; z < 524288; z += NCTA * NTHR)
        ((u32*)g_hA)[z] = 0;
    // weight images, fp16 B-fragment order: [nt][lane][slot{b0,b1}]
    for (int b = blockIdx.x; b < 15360; b += NCTA) {
        int l, nblk, c;
        if (b < 3072) { l = 0; nblk = b / 96; c = b % 96; }
        else { int r = b - 3072; l = 1 + r / 4096; r %= 4096; nblk = r / 128; c = r % 128; }
        const int ntA_ = (l == 0) ? 32 : 64;
        const float* Wsrc; int kb;
        if (c < ntA_) { Wsrc = (l == 0) ? Wx0 : Wxr + (size_t)(l - 1) * 4194304; kb = c * 16; }
        else          { Wsrc = (l == 0) ? Wh0 : Whr + (size_t)(l - 1) * 4194304; kb = (c - ntA_) * 16; }
        u32* dst = g_W + (size_t)b * 1024;
        for (int gw = t; gw < 1024; gw += NTHR) {
            const int nt = gw >> 6, rem = gw & 63, ln = rem >> 1, reg = rem & 1;
            const int n = nt * 8 + (ln >> 2);
            const int zc = (n & 3) * 1024 + nblk * 32 + (n >> 2);
            const int k = kb + (ln & 3) * 2 + reg * 8;
            dst[gw] = pack2h(__ldg(&Wsrc[(size_t)k * 4096 + zc]),
                             __ldg(&Wsrc[(size_t)(k + 1) * 4096 + zc]), false);
        }
    }
    // x images, fp16 hi/lo A-fragment order
    for (int bb = blockIdx.x; bb < 16384; bb += NCTA) {
        const int s_ = bb >> 5, c_ = bb & 31;
        u32* dst = g_x + (size_t)bb * 1024;
        for (int gw = t; gw < 1024; gw += NTHR) {
            const int mt = gw >> 8, rem = gw & 255, hl = rem >> 7, ww = rem & 127;
            const int ln = ww >> 2, reg = ww & 3;
            const int row = mt * 16 + (ln >> 2) + (reg & 1) * 8;
            const int k   = c_ * 16 + (ln & 3) * 2 + (reg >> 1) * 8;
            const float* p = x + (size_t)s_ * 32768 + row * 512 + k;
            dst[gw] = pack2h(__ldg(p), __ldg(p + 1), hl != 0);
        }
    }
    __syncthreads();
    if (t == 0) {
        #pragma unroll
        for (int i = 0; i < 3; i++) {
            mbar_init(mbF + 8 * i, 1);
            mbar_init(mbEW + 8 * i, 8);
        }
        asm volatile("fence.proxy.async;" ::: "memory");
        __threadfence();
        unsigned gen = GEN();
        if (atomicAdd(&g_sync[0], 1u) == NCTA - 1u) {
            g_sync[0] = 0;
            __threadfence();
            GEN() = gen + 1u;
        } else {
            while (GEN() == gen) __nanosleep(64);
        }
        __threadfence();
    }
    __syncthreads();

    // ================= MAIN WAVEFRONT LOOP ==================================
    const int layer = blockIdx.x >> 5, nblk = blockIdx.x & 31;
    const int mp = wid & 1, nq = wid >> 1;       // warp tile: 2 m-tiles x 4 n-tiles
    const int gid = lane >> 2, tig = lane & 3;
    const int ntA = (layer == 0) ? 32 : 64;
    const int nc  = ntA + 64;
    const int nst = nc >> 2;                     // stages per wave: 24 or 32
    const size_t wbase = (layer == 0) ? (size_t)nblk * 96
                                      : 3072 + ((size_t)(layer - 1) * 32 + nblk) * 128;
    const float* bias = (layer == 0) ? b0 : br + (size_t)(layer - 1) * 4096;

    const int hp = t & 15;
    const int rowBase = (t >> 4) * 4;
    const int hcol0 = nblk * 32 + hp * 2;
    float b42[2][4];
    #pragma unroll
    for (int cc = 0; cc < 2; cc++)
        #pragma unroll
        for (int g = 0; g < 4; g++)
            b42[cc][g] = __ldg(bias + g * 1024 + ((hcol0 + cc) & 1023));
    float creg[4][2];
    #pragma unroll
    for (int i = 0; i < 4; i++) { creg[i][0] = 0.f; creg[i][1] = 0.f; }

    const int kchunk = hcol0 >> 4;
    const int kl = hcol0 & 15;
    const int tigk = (kl >> 1) & 3, regk = kl >> 3;

    int pwst = 0, pwlap = 0;   // W-producer cursor
    int cst = 0,  clap = 0;    // consumer cursor

    for (int w = 0; w < 512 + 3; w++) {
        const int s = w - layer;
        if (s >= 0 && s < 512) {
            const int prPrev = (w & 1) ^ 1, prCur = w & 1;

            if (wid == 8) {
                // ---- W producer: free-running, ring-backpressured only ----
                if (lane == 0) {
                    for (int i = 0; i < nst; i++) {
                        if (pwlap > 0) mbar_wait(mbEW + 8 * pwst, (u32)((pwlap - 1) & 1));
                        const u32 full = mbF + 8 * pwst;
                        mbar_expect(full, 16384u);
                        #pragma unroll
                        for (int q = 0; q < 4; q++)
                            bulk_cp(smb + (u32)pwst * 16384u + (u32)q * 4096u,
                                    g_W + (wbase + i * 4 + q) * 1024, 4096u, full);
                        if (++pwst == 3) { pwst = 0; pwlap++; }
                    }
                }
            } else {
                // ---- 8 compute warps; A fragments via __ldcg (L2-direct) ----
                const u32* a0 = (layer == 0) ? g_x + (size_t)s * 32768
                                             : &g_hA[prPrev][layer - 1][0];
                const u32* a1 = &g_hA[prPrev][layer][0];

                float acc[2][4][4];
                #pragma unroll
                for (int m = 0; m < 2; m++)
                    #pragma unroll
                    for (int tt = 0; tt < 4; tt++)
                        #pragma unroll
                        for (int r = 0; r < 4; r++) acc[m][tt][r] = 0.f;

                uint4 fr[2][4];   // [buf][m*2 + hi/lo]
                auto ldA = [&](int buf, int c) {
                    const u32* A = (c < ntA) ? a0 + (size_t)c * 1024
                                             : a1 + (size_t)(c - ntA) * 1024;
                    #pragma unroll
                    for (int m = 0; m < 2; m++) {
                        const int mt = mp * 2 + m;
                        fr[buf][m * 2 + 0] = __ldcg((const uint4*)&A[(mt * 2 + 0) * 128 + lane * 4]);
                        fr[buf][m * 2 + 1] = __ldcg((const uint4*)&A[(mt * 2 + 1) * 128 + lane * 4]);
                    }
                };
                ldA(0, 0);
                ldA(1, 1);

                int c = 0;
                for (int i = 0; i < nst; i++) {
                    mbar_wait(mbF + 8 * cst, (u32)(clap & 1));
                    #pragma unroll
                    for (int q = 0; q < 4; q++, c++) {
                        const u32* W = sm + cst * 4096 + q * 1024;
                        const int buf = q & 1;   // c = i*4+q, i*4 even -> c&1 == q&1
                        #pragma unroll
                        for (int tt = 0; tt < 4; tt++) {
                            const int nt = nq * 4 + tt;
                            u32 bb[2];
                            *(ull*)bb = *(const ull*)&W[nt * 64 + lane * 2];
                            #pragma unroll
                            for (int m = 0; m < 2; m++) {
                                mma16816(acc[m][tt], (const u32*)&fr[buf][m * 2 + 0], bb);
                                mma16816(acc[m][tt], (const u32*)&fr[buf][m * 2 + 1], bb);
                            }
                        }
                        if (c + 2 < nc) ldA(buf, c + 2);
                    }
                    __syncwarp();
                    if (lane == 0) mbar_arrive(mbEW + 8 * cst);
                    if (++cst == 3) { cst = 0; clap++; }
                }

                #pragma unroll
                for (int m = 0; m < 2; m++) {
                    const int m0 = (mp * 2 + m) * 16;
                    #pragma unroll
                    for (int tt = 0; tt < 4; tt++) {
                        const int nb = (nq * 4 + tt) * 8 + tig * 2;
                        *(float2*)&zbuf[(m0 + gid) * 128 + nb] =
                            make_float2(acc[m][tt][0], acc[m][tt][1]);
                        *(float2*)&zbuf[(m0 + gid + 8) * 128 + nb] =
                            make_float2(acc[m][tt][2], acc[m][tt][3]);
                    }
                }
            }

            if (wid < 8) {
                CBAR();   // zbuf complete across compute warps
                u32* himg = &g_hA[prCur][layer][0];
                #pragma unroll
                for (int i = 0; i < 4; i++) {
                    const int r = rowBase + i;
                    const float4 z0 = *(const float4*)&zbuf[r * 128 + hp * 8];
                    const float4 z1 = *(const float4*)&zbuf[r * 128 + hp * 8 + 4];
                    float hn2[2], cn2[2];
                    {
                        const float ig = fsig(z0.x + b42[0][0]);
                        const float fg = fsig(z0.y + b42[0][1]);
                        const float og = fsig(z0.w + b42[0][3]);
                        const float cn = fg * creg[i][0] + ig * ftanh(z0.z + b42[0][2]);
                        hn2[0] = og * ftanh(cn); cn2[0] = cn; creg[i][0] = cn;
                    }
                    {
                        const float ig = fsig(z1.x + b42[1][0]);
                        const float fg = fsig(z1.y + b42[1][1]);
                        const float og = fsig(z1.w + b42[1][3]);
                        const float cn = fg * creg[i][1] + ig * ftanh(z1.z + b42[1][2]);
                        hn2[1] = og * ftanh(cn); cn2[1] = cn; creg[i][1] = cn;
                    }
                    const int rl = r & 15, mtr = r >> 4;
                    const int word = ((rl & 7) * 4 + tigk) * 4 + ((rl >> 3) | (regk << 1));
                    himg[kchunk * 1024 + (mtr * 2 + 0) * 128 + word] = pack2h(hn2[0], hn2[1], false);
                    himg[kchunk * 1024 + (mtr * 2 + 1) * 128 + word] = pack2h(hn2[0], hn2[1], true);
                    if (layer == 3)
                        *(float2*)&out[(size_t)s * BH_ + r * 1024 + hcol0] =
                            make_float2(hn2[0], hn2[1]);
                    if (s == 511) {
                        *(float2*)&out[HS_ + (size_t)layer * BH_ + r * 1024 + hcol0] =
                            make_float2(hn2[0], hn2[1]);
                        *(float2*)&out[HS_ + 262144ull + (size_t)layer * BH_ + r * 1024 + hcol0] =
                            make_float2(cn2[0], cn2[1]);
                    }
                }
            }
        }
        if (wid < 8 && w < 512 + 2) grid_sync_c();
    }
}

extern "C" void kernel_launch(void* const* d_in, const int* in_sizes, int n_in,
                              void* d_out, int out_size)
{
    const float* x   = (const float*)d_in[0];
    const float* Wx0 = (const float*)d_in[1];
    const float* Wh0 = (const float*)d_in[2];
    const float* b0  = (const float*)d_in[3];
    const float* Wxr = (const float*)d_in[4];
    const float* Whr = (const float*)d_in[5];
    const float* br  = (const float*)d_in[6];
    float* out = (float*)d_out;

    cudaFuncSetAttribute(lstm_persist, cudaFuncAttributeMaxDynamicSharedMemorySize, SMEM_DYN);
    lstm_persist<<<NCTA, NTHR, SMEM_DYN>>>(x, Wx0, Wh0, b0, Wxr, Whr, br, out);
}